// round 13
// baseline (speedup 1.0000x reference)
#include <cuda_runtime.h>
#include <cstdint>
#include <math.h>

// CausalGRNEMA exact chunked scan:
//  pass1: LC1=64 warp chunks (R4/R8 proven form), stores half (32-step) + full
//         aggregates.
//  pass2: serial combine -> exact carry-in at 32-step granularity (+ g_tab).
//  pass3: R4 inner body, LC3=32 -> 4096 warp tasks; block=128, bounds (128,6)
//         (reg cap 85 >= natural 80, no spill) -> ~24 resident warps/SM.
// State scaled: f = ema/OMA, f' = alpha*f + x^2.

#define ALPHA   0.99f
#define OMA     0.01f
#define EPSF    1e-6f
#define E0F     0.01f                     // EMAINIT/OMA

static constexpr int B    = 16;
static constexpr int T    = 8192;
static constexpr int C    = 512;
static constexpr int C4   = C / 4;        // 128 float4 columns
static constexpr int LC1  = 64;           // pass1 chunk
static constexpr int NCH1 = T / LC1;      // 128
static constexpr int LC3  = 32;           // pass3 chunk
static constexpr int NCH3 = T / LC3;      // 256
static constexpr int WPB1 = 8;
static constexpr int WPB3 = 4;            // 128-thread blocks
static constexpr int NTASK1 = B * NCH1;   // 2048
static constexpr int NTASK3 = B * NCH3;   // 4096

__device__ float2 g_tab[T];               // (EPS*D_t, EPS*sqrt(D_t))
__device__ float  g_Sf[NTASK1 * C];       // full-chunk aggregates (64 steps)
__device__ float  g_Sh[NTASK1 * C];       // half-chunk aggregates (32 steps)
__device__ float  g_Ein[NTASK3 * C];      // exact carry-in per 32-chunk

// ---- pass1: warp-autonomous local scan, half+full aggregates ----
__global__ __launch_bounds__(256, 3)
void pass1_kernel(const float* __restrict__ x) {
    const int warp = threadIdx.x >> 5;
    const int lane = threadIdx.x & 31;
    const int task = blockIdx.x * WPB1 + warp;
    const int b = task >> 7;              // / NCH1
    const int k = task & (NCH1 - 1);

    const float4* __restrict__ xb =
        (const float4*)x + ((size_t)b * T + (size_t)k * LC1) * C4 + lane;
    float4* __restrict__ Sh4 = (float4*)g_Sh + (size_t)task * C4 + lane;

    float4 f[4], cur[4], nxt[4];
    #pragma unroll
    for (int j = 0; j < 4; j++) f[j] = make_float4(0.f, 0.f, 0.f, 0.f);
    #pragma unroll
    for (int j = 0; j < 4; j++) cur[j] = xb[j * 32];

    for (int t = 0; t < LC1; t++) {
        if (t + 1 < LC1) {
            #pragma unroll
            for (int j = 0; j < 4; j++) nxt[j] = xb[(size_t)(t + 1) * C4 + j * 32];
        }
        #pragma unroll
        for (int j = 0; j < 4; j++) {
            f[j].x = fmaf(ALPHA, f[j].x, cur[j].x * cur[j].x);
            f[j].y = fmaf(ALPHA, f[j].y, cur[j].y * cur[j].y);
            f[j].z = fmaf(ALPHA, f[j].z, cur[j].z * cur[j].z);
            f[j].w = fmaf(ALPHA, f[j].w, cur[j].w * cur[j].w);
        }
        if (t == LC3 - 1) {               // half-chunk aggregate
            #pragma unroll
            for (int j = 0; j < 4; j++) Sh4[j * 32] = f[j];
        }
        #pragma unroll
        for (int j = 0; j < 4; j++) cur[j] = nxt[j];
    }
    float4* __restrict__ Sf4 = (float4*)g_Sf + (size_t)task * C4 + lane;
    #pragma unroll
    for (int j = 0; j < 4; j++) Sf4[j * 32] = f[j];
}

// ---- pass2: build g_tab + exact carry combine at 32-step granularity ----
__global__ void pass2_kernel() {
    const int idx = blockIdx.x * blockDim.x + threadIdx.x;  // 0..B*C-1 (== T)
    if (idx < T) {
        double D = 1.0 - exp((double)(idx + 1) * log(0.99)) + 1e-6;
        g_tab[idx] = make_float2((float)(1e-6 * D), (float)(1e-6 * sqrt(D)));
    }
    if (idx >= B * C) return;
    const int b = idx / C;
    const int c = idx % C;
    const float a32 = (float)exp(32.0 * log(0.99));
    const float a64 = a32 * a32;
    float E = E0F;                        // f-units
    #pragma unroll 4
    for (int k = 0; k < NCH1; k++) {
        const size_t o1 = ((size_t)b * NCH1 + k) * C + c;
        const size_t o3 = ((size_t)b * NCH3 + 2 * k) * C + c;
        g_Ein[o3]     = E;
        g_Ein[o3 + C] = fmaf(a32, E, g_Sh[o1]);
        E = fmaf(a64, E, g_Sf[o1]);
    }
}

// ---- pass3: warp-autonomous rescan (LC3=32), 128-thread blocks, occ 6 ----
__global__ __launch_bounds__(128, 6)
void pass3_kernel(const float* __restrict__ x,
                  const float* __restrict__ gamma,
                  const float* __restrict__ beta,
                  float* __restrict__ y) {
    __shared__ float4 sg[C4], sb[C4];
    {
        const int tid = threadIdx.x;
        sg[tid] = ((const float4*)gamma)[tid];
        sb[tid] = ((const float4*)beta)[tid];
    }
    __syncthreads();   // once

    const int warp = threadIdx.x >> 5;
    const int lane = threadIdx.x & 31;
    const int task = blockIdx.x * WPB3 + warp;
    const int b = task >> 8;              // / NCH3 (=256)
    const int k = task & (NCH3 - 1);
    const int tbase = k * LC3;

    const float4* __restrict__ xb =
        (const float4*)x + ((size_t)b * T + tbase) * C4 + lane;
    float4* __restrict__ yb =
        (float4*)y + ((size_t)b * T + tbase) * C4 + lane;

    float4 f[4];
    {
        const float4* __restrict__ E4 = (const float4*)g_Ein + (size_t)task * C4 + lane;
        #pragma unroll
        for (int j = 0; j < 4; j++) f[j] = E4[j * 32];
    }

    float4 cur[4], nxt[4];
    #pragma unroll
    for (int j = 0; j < 4; j++) cur[j] = xb[j * 32];

    for (int t = 0; t < LC3; t++) {
        if (t + 1 < LC3) {
            #pragma unroll
            for (int j = 0; j < 4; j++) nxt[j] = xb[(size_t)(t + 1) * C4 + j * 32];
        }
        const float2 cs = g_tab[tbase + t];   // (EPS*D, EPS*sqrt(D))

        float4 s[4];
        float acc = 0.0f;
        #pragma unroll
        for (int j = 0; j < 4; j++) {
            f[j].x = fmaf(ALPHA, f[j].x, cur[j].x * cur[j].x);
            f[j].y = fmaf(ALPHA, f[j].y, cur[j].y * cur[j].y);
            f[j].z = fmaf(ALPHA, f[j].z, cur[j].z * cur[j].z);
            f[j].w = fmaf(ALPHA, f[j].w, cur[j].w * cur[j].w);
            float vx = fmaf(OMA, f[j].x, cs.x);
            float vy = fmaf(OMA, f[j].y, cs.x);
            float vz = fmaf(OMA, f[j].z, cs.x);
            float vw = fmaf(OMA, f[j].w, cs.x);
            s[j].x = __frsqrt_rn(vx) * vx;    // = sqrt(vx)
            s[j].y = __frsqrt_rn(vy) * vy;
            s[j].z = __frsqrt_rn(vz) * vz;
            s[j].w = __frsqrt_rn(vw) * vw;
            acc += (s[j].x + s[j].y) + (s[j].z + s[j].w);
        }
        acc += __shfl_xor_sync(0xffffffffu, acc, 16);
        acc += __shfl_xor_sync(0xffffffffu, acc, 8);
        acc += __shfl_xor_sync(0xffffffffu, acc, 4);
        acc += __shfl_xor_sync(0xffffffffu, acc, 2);
        acc += __shfl_xor_sync(0xffffffffu, acc, 1);

        // n_c = s_c / (mean + EPS*sqrt(D)); y = x*(1 + gamma*n) + beta
        const float inv = __fdividef(1.0f, fmaf(acc, 1.0f / C, cs.y));

        #pragma unroll
        for (int j = 0; j < 4; j++) {
            const float4 g4 = sg[lane + j * 32];
            const float4 b4 = sb[lane + j * 32];
            float4 o;
            o.x = fmaf(cur[j].x, fmaf(g4.x, s[j].x * inv, 1.0f), b4.x);
            o.y = fmaf(cur[j].y, fmaf(g4.y, s[j].y * inv, 1.0f), b4.y);
            o.z = fmaf(cur[j].z, fmaf(g4.z, s[j].z * inv, 1.0f), b4.z);
            o.w = fmaf(cur[j].w, fmaf(g4.w, s[j].w * inv, 1.0f), b4.w);
            yb[(size_t)t * C4 + j * 32] = o;
        }
        #pragma unroll
        for (int j = 0; j < 4; j++) cur[j] = nxt[j];
    }
}

extern "C" void kernel_launch(void* const* d_in, const int* in_sizes, int n_in,
                              void* d_out, int out_size) {
    const float* x     = (const float*)d_in[0];
    const float* gamma = (const float*)d_in[1];
    const float* beta  = (const float*)d_in[2];
    float* y           = (float*)d_out;

    pass1_kernel<<<NTASK1 / WPB1, 256>>>(x);
    pass2_kernel<<<(B * C + 255) / 256, 256>>>();
    pass3_kernel<<<NTASK3 / WPB3, 128>>>(x, gamma, beta, y);
}

// round 15
// speedup vs baseline: 1.2049x; 1.2049x over previous
#include <cuda_runtime.h>
#include <cstdint>
#include <math.h>

// CausalGRNEMA exact chunked scan:
//  pass1: per-(b,chunk) warp scans LC=64 steps from 0 -> aggregate S (R4 form)
//  pass2: serial combine over chunks -> exact carry-in per chunk (+ g_tab)
//  pass3: task = (b,chunk) handled by a WARP PAIR, 8 channels/lane each
//         -> 4096 warps (27.7/SM), ~55 regs, short chains. Pair combines the
//         channel sum via one smem slot + one named barrier per timestep
//         (parity double-buffered).
// State scaled: f = ema/OMA, f' = alpha*f + x^2.

#define ALPHA   0.99f
#define OMA     0.01f
#define EPSF    1e-6f
#define E0F     0.01f                     // EMAINIT/OMA

static constexpr int B  = 16;
static constexpr int T  = 8192;
static constexpr int C  = 512;
static constexpr int C4 = C / 4;          // 128 float4 columns
static constexpr int LC = 64;             // timesteps per task
static constexpr int NCH = T / LC;        // 128 chunks
static constexpr int NTASK = B * NCH;     // 2048 tasks
static constexpr int TPB3 = 4;            // tasks per block (pass3: 8 warps)

__device__ float2 g_tab[T];               // (EPS*D_t, EPS*sqrt(D_t))
__device__ float  g_S[NTASK * C];         // chunk aggregates (f-units)
__device__ float  g_Ein[NTASK * C];       // exact carry-in per chunk (f-units)

// ---- pass1: warp-autonomous local scan, aggregate only (R4 proven) ----
__global__ __launch_bounds__(256, 3)
void pass1_kernel(const float* __restrict__ x) {
    const int warp = threadIdx.x >> 5;
    const int lane = threadIdx.x & 31;
    const int task = blockIdx.x * 8 + warp;
    const int b = task >> 7;              // / NCH
    const int k = task & (NCH - 1);

    const float4* __restrict__ xb =
        (const float4*)x + ((size_t)b * T + (size_t)k * LC) * C4 + lane;

    float4 f[4], cur[4], nxt[4];
    #pragma unroll
    for (int j = 0; j < 4; j++) f[j] = make_float4(0.f, 0.f, 0.f, 0.f);
    #pragma unroll
    for (int j = 0; j < 4; j++) cur[j] = xb[j * 32];

    for (int t = 0; t < LC; t++) {
        if (t + 1 < LC) {
            #pragma unroll
            for (int j = 0; j < 4; j++) nxt[j] = xb[(size_t)(t + 1) * C4 + j * 32];
        }
        #pragma unroll
        for (int j = 0; j < 4; j++) {
            f[j].x = fmaf(ALPHA, f[j].x, cur[j].x * cur[j].x);
            f[j].y = fmaf(ALPHA, f[j].y, cur[j].y * cur[j].y);
            f[j].z = fmaf(ALPHA, f[j].z, cur[j].z * cur[j].z);
            f[j].w = fmaf(ALPHA, f[j].w, cur[j].w * cur[j].w);
        }
        #pragma unroll
        for (int j = 0; j < 4; j++) cur[j] = nxt[j];
    }
    float4* __restrict__ S4 = (float4*)g_S + (size_t)task * C4 + lane;
    #pragma unroll
    for (int j = 0; j < 4; j++) S4[j * 32] = f[j];
}

// ---- pass2: build g_tab + exact carry combine across chunks (R4 proven) ----
__global__ void pass2_kernel() {
    const int idx = blockIdx.x * blockDim.x + threadIdx.x;  // 0..B*C-1 (== T)
    if (idx < T) {
        double D = 1.0 - exp((double)(idx + 1) * log(0.99)) + 1e-6;
        g_tab[idx] = make_float2((float)(1e-6 * D), (float)(1e-6 * sqrt(D)));
    }
    if (idx >= B * C) return;
    const int b = idx / C;
    const int c = idx % C;
    const float aL = (float)exp((double)LC * log(0.99));
    float E = E0F;                        // f-units
    #pragma unroll 8
    for (int k = 0; k < NCH; k++) {
        const size_t o = ((size_t)b * NCH + k) * C + c;
        g_Ein[o] = E;
        E = fmaf(aL, E, g_S[o]);
    }
}

// ---- pass3: warp-pair per task, 8 ch/lane, named-barrier pair combine ----
__global__ __launch_bounds__(256, 3)
void pass3_kernel(const float* __restrict__ x,
                  const float* __restrict__ gamma,
                  const float* __restrict__ beta,
                  float* __restrict__ y) {
    __shared__ float4 sg[C4], sb[C4];
    __shared__ float  part[TPB3][2][2];   // [pair][parity][half]
    {
        const int tid = threadIdx.x;
        if (tid < C4)       sg[tid]      = ((const float4*)gamma)[tid];
        else                sb[tid - C4] = ((const float4*)beta)[tid - C4];
    }
    __syncthreads();   // once

    const int warp = threadIdx.x >> 5;
    const int lane = threadIdx.x & 31;
    const int pair = warp >> 1;           // 0..3
    const int half = warp & 1;            // which 256-channel half
    const int task = blockIdx.x * TPB3 + pair;
    const int b = task >> 7;              // / NCH
    const int k = task & (NCH - 1);
    const int tbase = k * LC;
    const int col0 = half * 64 + lane;    // float4 column of j=0 (j=1 at +32)

    const float4* __restrict__ xb =
        (const float4*)x + ((size_t)b * T + tbase) * C4 + col0;
    float4* __restrict__ yb =
        (float4*)y + ((size_t)b * T + tbase) * C4 + col0;

    float4 f[2];
    {
        const float4* __restrict__ E4 = (const float4*)g_Ein + (size_t)task * C4 + col0;
        #pragma unroll
        for (int j = 0; j < 2; j++) f[j] = E4[j * 32];
    }

    float4 cur[2], nxt[2];
    #pragma unroll
    for (int j = 0; j < 2; j++) cur[j] = xb[j * 32];

    for (int t = 0; t < LC; t++) {
        if (t + 1 < LC) {
            #pragma unroll
            for (int j = 0; j < 2; j++) nxt[j] = xb[(size_t)(t + 1) * C4 + j * 32];
        }
        const float2 cs = g_tab[tbase + t];   // (EPS*D, EPS*sqrt(D))

        float4 s[2];
        float acc = 0.0f;
        #pragma unroll
        for (int j = 0; j < 2; j++) {
            f[j].x = fmaf(ALPHA, f[j].x, cur[j].x * cur[j].x);
            f[j].y = fmaf(ALPHA, f[j].y, cur[j].y * cur[j].y);
            f[j].z = fmaf(ALPHA, f[j].z, cur[j].z * cur[j].z);
            f[j].w = fmaf(ALPHA, f[j].w, cur[j].w * cur[j].w);
            float vx = fmaf(OMA, f[j].x, cs.x);
            float vy = fmaf(OMA, f[j].y, cs.x);
            float vz = fmaf(OMA, f[j].z, cs.x);
            float vw = fmaf(OMA, f[j].w, cs.x);
            s[j].x = __frsqrt_rn(vx) * vx;    // = sqrt(vx)
            s[j].y = __frsqrt_rn(vy) * vy;
            s[j].z = __frsqrt_rn(vz) * vz;
            s[j].w = __frsqrt_rn(vw) * vw;
            acc += (s[j].x + s[j].y) + (s[j].z + s[j].w);
        }
        acc += __shfl_xor_sync(0xffffffffu, acc, 16);
        acc += __shfl_xor_sync(0xffffffffu, acc, 8);
        acc += __shfl_xor_sync(0xffffffffu, acc, 4);
        acc += __shfl_xor_sync(0xffffffffu, acc, 2);
        acc += __shfl_xor_sync(0xffffffffu, acc, 1);

        // pair combine: one STS + one named barrier (parity double-buffer)
        if (lane == 0) part[pair][t & 1][half] = acc;
        asm volatile("bar.sync %0, 64;" :: "r"(pair + 1));
        const float tot = part[pair][t & 1][0] + part[pair][t & 1][1];

        // n_c = s_c / (mean + EPS*sqrt(D)); y = x*(1 + gamma*n) + beta
        const float inv = __fdividef(1.0f, fmaf(tot, 1.0f / C, cs.y));

        #pragma unroll
        for (int j = 0; j < 2; j++) {
            const float4 g4 = sg[col0 + j * 32];
            const float4 b4 = sb[col0 + j * 32];
            float4 o;
            o.x = fmaf(cur[j].x, fmaf(g4.x, s[j].x * inv, 1.0f), b4.x);
            o.y = fmaf(cur[j].y, fmaf(g4.y, s[j].y * inv, 1.0f), b4.y);
            o.z = fmaf(cur[j].z, fmaf(g4.z, s[j].z * inv, 1.0f), b4.z);
            o.w = fmaf(cur[j].w, fmaf(g4.w, s[j].w * inv, 1.0f), b4.w);
            yb[(size_t)t * C4 + j * 32] = o;
        }
        #pragma unroll
        for (int j = 0; j < 2; j++) cur[j] = nxt[j];
    }
}

extern "C" void kernel_launch(void* const* d_in, const int* in_sizes, int n_in,
                              void* d_out, int out_size) {
    const float* x     = (const float*)d_in[0];
    const float* gamma = (const float*)d_in[1];
    const float* beta  = (const float*)d_in[2];
    float* y           = (float*)d_out;

    pass1_kernel<<<NTASK / 8, 256>>>(x);
    pass2_kernel<<<(B * C + 255) / 256, 256>>>();
    pass3_kernel<<<NTASK / TPB3, 256>>>(x, gamma, beta, y);
}

// round 16
// speedup vs baseline: 1.3043x; 1.0825x over previous
#include <cuda_runtime.h>
#include <cstdint>
#include <math.h>

// CausalGRNEMA exact chunked scan (R4 structure + L2-reuse scheduling):
//  pass1: per-(b,chunk) warp scans LC=64 steps from 0 -> aggregate S.
//         Forward task order; S stored with .cs (evict-first).
//  pass2: serial combine over chunks -> exact carry-in per chunk (+ g_tab).
//  pass3: identical body to R4 but tasks iterated in REVERSE so its first
//         ~100MB of x reads hit the L2 tail left by pass1; y stored with .cs
//         so the write stream doesn't evict x.
// State scaled: f = ema/OMA, f' = alpha*f + x^2.

#define ALPHA   0.99f
#define OMA     0.01f
#define EPSF    1e-6f
#define E0F     0.01f                     // EMAINIT/OMA

static constexpr int B  = 16;
static constexpr int T  = 8192;
static constexpr int C  = 512;
static constexpr int C4 = C / 4;          // 128 float4 columns
static constexpr int LC = 64;             // timesteps per warp task
static constexpr int NCH = T / LC;        // 128 chunks
static constexpr int WPB = 8;             // warps per block
static constexpr int NTASK = B * NCH;     // 2048 warp tasks

__device__ float2 g_tab[T];               // (EPS*D_t, EPS*sqrt(D_t))
__device__ float  g_S[NTASK * C];         // chunk aggregates (f-units)
__device__ float  g_Ein[NTASK * C];       // exact carry-in per chunk (f-units)

// ---- pass1: warp-autonomous local scan, aggregate only ----
__global__ __launch_bounds__(256, 3)
void pass1_kernel(const float* __restrict__ x) {
    const int warp = threadIdx.x >> 5;
    const int lane = threadIdx.x & 31;
    const int task = blockIdx.x * WPB + warp;
    const int b = task >> 7;              // / NCH
    const int k = task & (NCH - 1);

    const float4* __restrict__ xb =
        (const float4*)x + ((size_t)b * T + (size_t)k * LC) * C4 + lane;

    float4 f[4], cur[4], nxt[4];
    #pragma unroll
    for (int j = 0; j < 4; j++) f[j] = make_float4(0.f, 0.f, 0.f, 0.f);
    #pragma unroll
    for (int j = 0; j < 4; j++) cur[j] = xb[j * 32];

    for (int t = 0; t < LC; t++) {
        if (t + 1 < LC) {
            #pragma unroll
            for (int j = 0; j < 4; j++) nxt[j] = xb[(size_t)(t + 1) * C4 + j * 32];
        }
        #pragma unroll
        for (int j = 0; j < 4; j++) {
            f[j].x = fmaf(ALPHA, f[j].x, cur[j].x * cur[j].x);
            f[j].y = fmaf(ALPHA, f[j].y, cur[j].y * cur[j].y);
            f[j].z = fmaf(ALPHA, f[j].z, cur[j].z * cur[j].z);
            f[j].w = fmaf(ALPHA, f[j].w, cur[j].w * cur[j].w);
        }
        #pragma unroll
        for (int j = 0; j < 4; j++) cur[j] = nxt[j];
    }
    float4* S4 = (float4*)g_S + (size_t)task * C4 + lane;
    #pragma unroll
    for (int j = 0; j < 4; j++) __stcs(S4 + j * 32, f[j]);   // evict-first
}

// ---- pass2: build g_tab + exact carry combine across chunks ----
__global__ void pass2_kernel() {
    const int idx = blockIdx.x * blockDim.x + threadIdx.x;  // 0..B*C-1 (== T)
    if (idx < T) {
        double D = 1.0 - exp((double)(idx + 1) * log(0.99)) + 1e-6;
        g_tab[idx] = make_float2((float)(1e-6 * D), (float)(1e-6 * sqrt(D)));
    }
    if (idx >= B * C) return;
    const int b = idx / C;
    const int c = idx % C;
    const float aL = (float)exp((double)LC * log(0.99));
    float E = E0F;                        // f-units
    #pragma unroll 8
    for (int k = 0; k < NCH; k++) {
        const size_t o = ((size_t)b * NCH + k) * C + c;
        g_Ein[o] = E;
        E = fmaf(aL, E, __ldcs(&g_S[o]));
    }
}

// ---- pass3: warp-autonomous rescan, REVERSE task order, .cs stores ----
__global__ __launch_bounds__(256, 2)
void pass3_kernel(const float* __restrict__ x,
                  const float* __restrict__ gamma,
                  const float* __restrict__ beta,
                  float* __restrict__ y) {
    __shared__ float4 sg[C4], sb[C4];
    {
        const int tid = threadIdx.x;
        if (tid < C4)       sg[tid]      = ((const float4*)gamma)[tid];
        else                sb[tid - C4] = ((const float4*)beta)[tid - C4];
    }
    __syncthreads();   // once

    const int warp = threadIdx.x >> 5;
    const int lane = threadIdx.x & 31;
    // reverse: first-launched blocks take the L2-hot tail of x
    const int task = (NTASK - 1) - (blockIdx.x * WPB + warp);
    const int b = task >> 7;
    const int k = task & (NCH - 1);
    const int tbase = k * LC;

    const float4* __restrict__ xb =
        (const float4*)x + ((size_t)b * T + tbase) * C4 + lane;
    float4* __restrict__ yb =
        (float4*)y + ((size_t)b * T + tbase) * C4 + lane;

    float4 f[4];
    {
        const float4* __restrict__ E4 = (const float4*)g_Ein + (size_t)task * C4 + lane;
        #pragma unroll
        for (int j = 0; j < 4; j++) f[j] = E4[j * 32];
    }

    float4 cur[4], nxt[4];
    #pragma unroll
    for (int j = 0; j < 4; j++) cur[j] = xb[j * 32];

    for (int t = 0; t < LC; t++) {
        if (t + 1 < LC) {
            #pragma unroll
            for (int j = 0; j < 4; j++) nxt[j] = xb[(size_t)(t + 1) * C4 + j * 32];
        }
        const float2 cs = g_tab[tbase + t];   // (EPS*D, EPS*sqrt(D))

        float4 s[4];
        float acc = 0.0f;
        #pragma unroll
        for (int j = 0; j < 4; j++) {
            f[j].x = fmaf(ALPHA, f[j].x, cur[j].x * cur[j].x);
            f[j].y = fmaf(ALPHA, f[j].y, cur[j].y * cur[j].y);
            f[j].z = fmaf(ALPHA, f[j].z, cur[j].z * cur[j].z);
            f[j].w = fmaf(ALPHA, f[j].w, cur[j].w * cur[j].w);
            float vx = fmaf(OMA, f[j].x, cs.x);
            float vy = fmaf(OMA, f[j].y, cs.x);
            float vz = fmaf(OMA, f[j].z, cs.x);
            float vw = fmaf(OMA, f[j].w, cs.x);
            s[j].x = __frsqrt_rn(vx) * vx;    // = sqrt(vx)
            s[j].y = __frsqrt_rn(vy) * vy;
            s[j].z = __frsqrt_rn(vz) * vz;
            s[j].w = __frsqrt_rn(vw) * vw;
            acc += (s[j].x + s[j].y) + (s[j].z + s[j].w);
        }
        acc += __shfl_xor_sync(0xffffffffu, acc, 16);
        acc += __shfl_xor_sync(0xffffffffu, acc, 8);
        acc += __shfl_xor_sync(0xffffffffu, acc, 4);
        acc += __shfl_xor_sync(0xffffffffu, acc, 2);
        acc += __shfl_xor_sync(0xffffffffu, acc, 1);

        // n_c = s_c / (mean + EPS*sqrt(D)); y = x*(1 + gamma*n) + beta
        const float inv = __fdividef(1.0f, fmaf(acc, 1.0f / C, cs.y));

        #pragma unroll
        for (int j = 0; j < 4; j++) {
            const float4 g4 = sg[lane + j * 32];
            const float4 b4 = sb[lane + j * 32];
            float4 o;
            o.x = fmaf(cur[j].x, fmaf(g4.x, s[j].x * inv, 1.0f), b4.x);
            o.y = fmaf(cur[j].y, fmaf(g4.y, s[j].y * inv, 1.0f), b4.y);
            o.z = fmaf(cur[j].z, fmaf(g4.z, s[j].z * inv, 1.0f), b4.z);
            o.w = fmaf(cur[j].w, fmaf(g4.w, s[j].w * inv, 1.0f), b4.w);
            __stcs(yb + (size_t)t * C4 + j * 32, o);   // evict-first write
        }
        #pragma unroll
        for (int j = 0; j < 4; j++) cur[j] = nxt[j];
    }
}

extern "C" void kernel_launch(void* const* d_in, const int* in_sizes, int n_in,
                              void* d_out, int out_size) {
    const float* x     = (const float*)d_in[0];
    const float* gamma = (const float*)d_in[1];
    const float* beta  = (const float*)d_in[2];
    float* y           = (float*)d_out;

    pass1_kernel<<<NTASK / WPB, 256>>>(x);
    pass2_kernel<<<(B * C + 255) / 256, 256>>>();
    pass3_kernel<<<NTASK / WPB, 256>>>(x, gamma, beta, y);
}

// round 17
// speedup vs baseline: 1.3145x; 1.0079x over previous
#include <cuda_runtime.h>
#include <cstdint>
#include <math.h>

// CausalGRNEMA exact chunked scan (R4 structure + g_tab de-thrash):
//  pass1: per-(b,chunk) warp scans LC=64 steps from 0 -> aggregate S (proven).
//  pass2: serial combine over chunks -> exact carry-in per chunk (+ g_tab).
//  pass3: R4 body, but (1) g_tab staged to SMEM per block (the per-timestep
//         constant load was a dependent LDG thrashed out of L1 by the x
//         stream -> serial L2 round-trip every iteration), and (2) x loads
//         use __ldcs (evict-first) so the stream stops evicting L1.
// State scaled: f = ema/OMA, f' = alpha*f + x^2.

#define ALPHA   0.99f
#define OMA     0.01f
#define EPSF    1e-6f
#define E0F     0.01f                     // EMAINIT/OMA

static constexpr int B  = 16;
static constexpr int T  = 8192;
static constexpr int C  = 512;
static constexpr int C4 = C / 4;          // 128 float4 columns
static constexpr int LC = 64;             // timesteps per warp task
static constexpr int NCH = T / LC;        // 128 chunks
static constexpr int WPB = 8;             // warps per block
static constexpr int NTASK = B * NCH;     // 2048 warp tasks

__device__ float2 g_tab[T];               // (EPS*D_t, EPS*sqrt(D_t))
__device__ float  g_S[NTASK * C];         // chunk aggregates (f-units)
__device__ float  g_Ein[NTASK * C];       // exact carry-in per chunk (f-units)

// ---- pass1: warp-autonomous local scan, aggregate only (R4 proven) ----
__global__ __launch_bounds__(256, 3)
void pass1_kernel(const float* __restrict__ x) {
    const int warp = threadIdx.x >> 5;
    const int lane = threadIdx.x & 31;
    const int task = blockIdx.x * WPB + warp;
    const int b = task >> 7;              // / NCH
    const int k = task & (NCH - 1);

    const float4* __restrict__ xb =
        (const float4*)x + ((size_t)b * T + (size_t)k * LC) * C4 + lane;

    float4 f[4], cur[4], nxt[4];
    #pragma unroll
    for (int j = 0; j < 4; j++) f[j] = make_float4(0.f, 0.f, 0.f, 0.f);
    #pragma unroll
    for (int j = 0; j < 4; j++) cur[j] = xb[j * 32];

    for (int t = 0; t < LC; t++) {
        if (t + 1 < LC) {
            #pragma unroll
            for (int j = 0; j < 4; j++) nxt[j] = xb[(size_t)(t + 1) * C4 + j * 32];
        }
        #pragma unroll
        for (int j = 0; j < 4; j++) {
            f[j].x = fmaf(ALPHA, f[j].x, cur[j].x * cur[j].x);
            f[j].y = fmaf(ALPHA, f[j].y, cur[j].y * cur[j].y);
            f[j].z = fmaf(ALPHA, f[j].z, cur[j].z * cur[j].z);
            f[j].w = fmaf(ALPHA, f[j].w, cur[j].w * cur[j].w);
        }
        #pragma unroll
        for (int j = 0; j < 4; j++) cur[j] = nxt[j];
    }
    float4* __restrict__ S4 = (float4*)g_S + (size_t)task * C4 + lane;
    #pragma unroll
    for (int j = 0; j < 4; j++) S4[j * 32] = f[j];
}

// ---- pass2: build g_tab + exact carry combine across chunks ----
__global__ void pass2_kernel() {
    const int idx = blockIdx.x * blockDim.x + threadIdx.x;  // 0..B*C-1 (== T)
    if (idx < T) {
        double D = 1.0 - exp((double)(idx + 1) * log(0.99)) + 1e-6;
        g_tab[idx] = make_float2((float)(1e-6 * D), (float)(1e-6 * sqrt(D)));
    }
    if (idx >= B * C) return;
    const int b = idx / C;
    const int c = idx % C;
    const float aL = (float)exp((double)LC * log(0.99));
    float E = E0F;                        // f-units
    #pragma unroll 8
    for (int k = 0; k < NCH; k++) {
        const size_t o = ((size_t)b * NCH + k) * C + c;
        g_Ein[o] = E;
        E = fmaf(aL, E, g_S[o]);
    }
}

// ---- pass3: warp-autonomous rescan; smem-staged tab; evict-first x stream ----
__global__ __launch_bounds__(256, 2)
void pass3_kernel(const float* __restrict__ x,
                  const float* __restrict__ gamma,
                  const float* __restrict__ beta,
                  float* __restrict__ y) {
    __shared__ float4 sg[C4], sb[C4];
    __shared__ float2 tab_s[WPB * LC];    // per-warp chunk constants (4KB)

    const int warp = threadIdx.x >> 5;
    const int lane = threadIdx.x & 31;
    const int task = blockIdx.x * WPB + warp;
    const int b = task >> 7;
    const int k = task & (NCH - 1);
    const int tbase = k * LC;

    {
        const int tid = threadIdx.x;
        if (tid < C4)       sg[tid]      = ((const float4*)gamma)[tid];
        else                sb[tid - C4] = ((const float4*)beta)[tid - C4];
        // each warp stages its own 64 constants (2 per lane)
        tab_s[warp * LC + lane]      = g_tab[tbase + lane];
        tab_s[warp * LC + 32 + lane] = g_tab[tbase + 32 + lane];
    }
    __syncthreads();   // once

    const float4* __restrict__ xb =
        (const float4*)x + ((size_t)b * T + tbase) * C4 + lane;
    float4* __restrict__ yb =
        (float4*)y + ((size_t)b * T + tbase) * C4 + lane;
    const float2* __restrict__ tw = tab_s + warp * LC;

    float4 f[4];
    {
        const float4* __restrict__ E4 = (const float4*)g_Ein + (size_t)task * C4 + lane;
        #pragma unroll
        for (int j = 0; j < 4; j++) f[j] = E4[j * 32];
    }

    float4 cur[4], nxt[4];
    #pragma unroll
    for (int j = 0; j < 4; j++) cur[j] = __ldcs(xb + j * 32);

    for (int t = 0; t < LC; t++) {
        if (t + 1 < LC) {
            #pragma unroll
            for (int j = 0; j < 4; j++)
                nxt[j] = __ldcs(xb + (size_t)(t + 1) * C4 + j * 32);
        }
        const float2 cs = tw[t];          // broadcast LDS, 29 cyc, never thrashed

        float4 s[4];
        float acc = 0.0f;
        #pragma unroll
        for (int j = 0; j < 4; j++) {
            f[j].x = fmaf(ALPHA, f[j].x, cur[j].x * cur[j].x);
            f[j].y = fmaf(ALPHA, f[j].y, cur[j].y * cur[j].y);
            f[j].z = fmaf(ALPHA, f[j].z, cur[j].z * cur[j].z);
            f[j].w = fmaf(ALPHA, f[j].w, cur[j].w * cur[j].w);
            float vx = fmaf(OMA, f[j].x, cs.x);
            float vy = fmaf(OMA, f[j].y, cs.x);
            float vz = fmaf(OMA, f[j].z, cs.x);
            float vw = fmaf(OMA, f[j].w, cs.x);
            s[j].x = __frsqrt_rn(vx) * vx;    // = sqrt(vx)
            s[j].y = __frsqrt_rn(vy) * vy;
            s[j].z = __frsqrt_rn(vz) * vz;
            s[j].w = __frsqrt_rn(vw) * vw;
            acc += (s[j].x + s[j].y) + (s[j].z + s[j].w);
        }
        acc += __shfl_xor_sync(0xffffffffu, acc, 16);
        acc += __shfl_xor_sync(0xffffffffu, acc, 8);
        acc += __shfl_xor_sync(0xffffffffu, acc, 4);
        acc += __shfl_xor_sync(0xffffffffu, acc, 2);
        acc += __shfl_xor_sync(0xffffffffu, acc, 1);

        // n_c = s_c / (mean + EPS*sqrt(D)); y = x*(1 + gamma*n) + beta
        const float inv = __fdividef(1.0f, fmaf(acc, 1.0f / C, cs.y));

        #pragma unroll
        for (int j = 0; j < 4; j++) {
            const float4 g4 = sg[lane + j * 32];
            const float4 b4 = sb[lane + j * 32];
            float4 o;
            o.x = fmaf(cur[j].x, fmaf(g4.x, s[j].x * inv, 1.0f), b4.x);
            o.y = fmaf(cur[j].y, fmaf(g4.y, s[j].y * inv, 1.0f), b4.y);
            o.z = fmaf(cur[j].z, fmaf(g4.z, s[j].z * inv, 1.0f), b4.z);
            o.w = fmaf(cur[j].w, fmaf(g4.w, s[j].w * inv, 1.0f), b4.w);
            yb[(size_t)t * C4 + j * 32] = o;
        }
        #pragma unroll
        for (int j = 0; j < 4; j++) cur[j] = nxt[j];
    }
}

extern "C" void kernel_launch(void* const* d_in, const int* in_sizes, int n_in,
                              void* d_out, int out_size) {
    const float* x     = (const float*)d_in[0];
    const float* gamma = (const float*)d_in[1];
    const float* beta  = (const float*)d_in[2];
    float* y           = (float*)d_out;

    pass1_kernel<<<NTASK / WPB, 256>>>(x);
    pass2_kernel<<<(B * C + 255) / 256, 256>>>();
    pass3_kernel<<<NTASK / WPB, 256>>>(x, gamma, beta, y);
}